// round 9
// baseline (speedup 1.0000x reference)
#include <cuda_runtime.h>
#include <math.h>

#define NN 2048
#define FF 128
#define HH 32
#define EE 65536
#define PP 768
#define FULL 0xffffffffu
#define GRID 148
#define TPA 1024
#define TPB 512
#define NTA (GRID * TPA)
#define HALFSLOTS (GRID * TPB / 2)   // 37888 edge-slots per pass

typedef unsigned long long ull;

// ---------------- device scratch (no allocations allowed) ----------------
// d_M: 0 = empty, else edge_id+1. Zero at module load. Each launch REWRITES
// exactly the same slot set {(src[e],dst[e])} before any read, so stale values
// from a previous replay are always overwritten -> no cleanup pass needed.
__device__ int   d_M[NN * NN];
__device__ int   d_deg[NN];
__device__ int   d_cnt[NN];
__device__ int   d_curs[NN];
__device__ int   d_curd[NN];
__device__ int   d_outptr[NN + 1];
__device__ int   d_inptr[NN + 1];
__device__ int   d_outlist[EE];
__device__ int   d_inlist[EE];
__device__ float d_dinv[NN];
__device__ float d_t1[NN * HH];
__device__ float d_t2[NN * HH];
__device__ __align__(16) float d_h[NN * HH];
__device__ __align__(16) float d_x1[EE * HH];
__device__ __align__(16) float d_x2[EE * HH];
__device__ unsigned          bar_cnt;
__device__ volatile unsigned bar_gen;

__device__ __forceinline__ void gridbar() {
    __syncthreads();
    if (threadIdx.x == 0) {
        __threadfence();
        unsigned g = bar_gen;
        if (atomicAdd(&bar_cnt, 1u) == GRID - 1u) {
            bar_cnt = 0;
            __threadfence();
            bar_gen = g + 1u;
        } else {
            while (bar_gen == g) __nanosleep(32);
        }
        __threadfence();
    }
    __syncthreads();
}

__device__ __forceinline__ float wsum(float v) {
    #pragma unroll
    for (int o = 16; o; o >>= 1) v += __shfl_xor_sync(FULL, v, o);
    return v;
}

__device__ __forceinline__ ull packf2(float lo, float hi) {
    ull r;
    asm("mov.b64 %0, {%1, %2};" : "=l"(r) : "f"(lo), "f"(hi));
    return r;
}
__device__ __forceinline__ void unpackf2(ull v, float& lo, float& hi) {
    asm("mov.b64 {%0, %1}, %2;" : "=f"(lo), "=f"(hi) : "l"(v));
}
__device__ __forceinline__ ull fma2(ull a, ull b, ull c) {
    ull d;
    asm("fma.rn.f32x2 %0, %1, %2, %3;" : "=l"(d) : "l"(a), "l"(b), "l"(c));
    return d;
}
__device__ __forceinline__ ull add2(ull a, ull b) {
    ull d;
    asm("add.rn.f32x2 %0, %1, %2;" : "=l"(d) : "l"(a), "l"(b));
    return d;
}
__device__ __forceinline__ ull mul2(ull a, ull b) {
    ull d;
    asm("mul.rn.f32x2 %0, %1, %2;" : "=l"(d) : "l"(a), "l"(b));
    return d;
}

__device__ __forceinline__ int wscan_incl(int v, int lane) {
    #pragma unroll
    for (int o = 1; o < 32; o <<= 1) {
        int n = __shfl_up_sync(FULL, v, o);
        if (lane >= o) v += n;
    }
    return v;
}

// ================= megaA: CSR build + both GCN layers =================
__global__ void __launch_bounds__(TPA, 1) megaA_k(
    const float* __restrict__ x,  const int* __restrict__ ei,
    const float* __restrict__ W1, const float* __restrict__ b1,
    const float* __restrict__ W2, const float* __restrict__ b2)
{
    __shared__ float SM[4096];
    __shared__ int wt[32], wt2[32];
    const int tid  = threadIdx.x;
    const int warp = tid >> 5, t = tid & 31;
    const int gtid = blockIdx.x * TPA + tid;
    const int* src = ei;
    const int* dst = ei + EE;

    // ---- P0: gemm1 (t1 = x @ W1) overlapped with degrees + M scatter ----
    for (int i = tid; i < FF * HH; i += TPA) SM[i] = W1[i];
    __syncthreads();
    for (int e = gtid; e < EE; e += NTA) {       // fire atomics first
        int s = src[e], d = dst[e];
        atomicAdd(&d_deg[d], 1);
        atomicAdd(&d_cnt[s], 1);
        d_M[s * NN + d] = e + 1;   // duplicate (s,d) race: value-equivalent winners
    }
    {
        int row = warp * GRID + blockIdx.x;      // balanced across blocks
        if (row < NN) {
            const float* xr = x + row * FF;
            float xa = xr[t], xb = xr[32 + t], xc = xr[64 + t], xd = xr[96 + t];
            float acc = 0.f;
            #pragma unroll
            for (int k = 0; k < 32; k++) {
                acc = fmaf(__shfl_sync(FULL, xa, k), SM[k * HH + t], acc);
                acc = fmaf(__shfl_sync(FULL, xb, k), SM[(k + 32) * HH + t], acc);
                acc = fmaf(__shfl_sync(FULL, xc, k), SM[(k + 64) * HH + t], acc);
                acc = fmaf(__shfl_sync(FULL, xd, k), SM[(k + 96) * HH + t], acc);
            }
            d_t1[row * HH + t] = acc;
        }
    }
    gridbar();

    // ---- P1: block 0 fast scans (warp-shfl based) + dinv ----
    if (blockIdx.x == 0) {
        int a = d_cnt[2 * tid], b = d_cnt[2 * tid + 1];
        int c = d_deg[2 * tid], dd = d_deg[2 * tid + 1];
        int v1 = a + b, v2 = c + dd;
        int sc1 = wscan_incl(v1, t);
        int sc2 = wscan_incl(v2, t);
        if (t == 31) { wt[warp] = sc1; wt2[warp] = sc2; }
        __syncthreads();
        if (warp == 0) {
            int x1 = wscan_incl(wt[t], t);
            int x2 = wscan_incl(wt2[t], t);
            wt[t] = x1; wt2[t] = x2;
        }
        __syncthreads();
        int base1 = warp ? wt[warp - 1] : 0;
        int incl1 = base1 + sc1, excl1 = incl1 - v1;
        d_outptr[2 * tid] = excl1;
        d_outptr[2 * tid + 1] = excl1 + a;
        if (tid == 1023) d_outptr[2048] = incl1;
        int base2 = warp ? wt2[warp - 1] : 0;
        int incl2 = base2 + sc2, excl2 = incl2 - v2;
        d_inptr[2 * tid] = excl2;
        d_inptr[2 * tid + 1] = excl2 + c;
        if (tid == 1023) d_inptr[2048] = incl2;
        d_dinv[2 * tid]     = rsqrtf((float)(c + 1));
        d_dinv[2 * tid + 1] = rsqrtf((float)(dd + 1));
    }
    gridbar();

    // ---- P2: fill both CSR lists; zero deg/cnt ----
    if (gtid < NN) { d_deg[gtid] = 0; d_cnt[gtid] = 0; }
    for (int e = gtid; e < EE; e += NTA) {
        int s = src[e], d = dst[e];
        int ob = d_outptr[s], ib = d_inptr[d];
        int s1 = atomicAdd(&d_curs[s], 1);
        int s2 = atomicAdd(&d_curd[d], 1);
        d_outlist[ob + s1] = e;
        d_inlist[ib + s2]  = s;
    }
    gridbar();

    // ---- P3: gather layer1 (2 warps/node, 4 rows in flight) + GEMM W2 ; zero cursors ----
    for (int i = tid; i < HH * HH; i += TPA) SM[i] = W2[i];
    if (gtid < NN) { d_curs[gtid] = 0; d_curd[gtid] = 0; }
    __syncthreads();
    {
        int pairid = warp >> 1, parity = warp & 1;
        int v = blockIdx.x * 16 + pairid;
        float part = 0.f;
        if (v < NN) {
            int st = d_inptr[v], en = d_inptr[v + 1];
            int i = st + parity;
            for (; i + 8 <= en; i += 8) {
                int s0 = d_inlist[i],     s1 = d_inlist[i + 2];
                int s2 = d_inlist[i + 4], s3 = d_inlist[i + 6];
                float f0 = d_t1[s0 * HH + t] * d_dinv[s0];
                float f1 = d_t1[s1 * HH + t] * d_dinv[s1];
                float f2 = d_t1[s2 * HH + t] * d_dinv[s2];
                float f3 = d_t1[s3 * HH + t] * d_dinv[s3];
                part += (f0 + f1) + (f2 + f3);
            }
            for (; i < en; i += 2) {
                int s = d_inlist[i];
                part = fmaf(d_t1[s * HH + t], d_dinv[s], part);
            }
        }
        if (parity && v < NN) SM[1024 + pairid * 32 + t] = part;
        __syncthreads();
        if (!parity && v < NN) {
            float di = d_dinv[v];
            float hv = (part + SM[1024 + pairid * 32 + t] + d_t1[v * HH + t] * di) * di + b1[t];
            float y = 0.f;
            #pragma unroll
            for (int k = 0; k < HH; k++)
                y = fmaf(__shfl_sync(FULL, hv, k), SM[k * HH + t], y);
            d_t2[v * HH + t] = y;
        }
    }
    gridbar();

    // ---- P4: gather layer2 -> h ----
    {
        int pairid = warp >> 1, parity = warp & 1;
        int v = blockIdx.x * 16 + pairid;
        float part = 0.f;
        if (v < NN) {
            int st = d_inptr[v], en = d_inptr[v + 1];
            int i = st + parity;
            for (; i + 8 <= en; i += 8) {
                int s0 = d_inlist[i],     s1 = d_inlist[i + 2];
                int s2 = d_inlist[i + 4], s3 = d_inlist[i + 6];
                float f0 = d_t2[s0 * HH + t] * d_dinv[s0];
                float f1 = d_t2[s1 * HH + t] * d_dinv[s1];
                float f2 = d_t2[s2 * HH + t] * d_dinv[s2];
                float f3 = d_t2[s3 * HH + t] * d_dinv[s3];
                part += (f0 + f1) + (f2 + f3);
            }
            for (; i < en; i += 2) {
                int s = d_inlist[i];
                part = fmaf(d_t2[s * HH + t], d_dinv[s], part);
            }
        }
        if (parity && v < NN) SM[pairid * 32 + t] = part;
        __syncthreads();
        if (!parity && v < NN) {
            float di = d_dinv[v];
            d_h[v * HH + t] = (part + SM[pairid * 32 + t] + d_t2[v * HH + t] * di) * di + b2[t];
        }
    }
}

// ================= megaB: 2-threads-per-edge MLP + posval =================
__global__ void __launch_bounds__(TPB, 1) megaB_k(
    const int* __restrict__ ei,  const int* __restrict__ pos,
    const float* __restrict__ m1w, const float* __restrict__ m1b,
    const float* __restrict__ m1g, const float* __restrict__ m1be,
    const float* __restrict__ m2w, const float* __restrict__ m2b,
    const float* __restrict__ m2g, const float* __restrict__ m2be,
    const float* __restrict__ w31, const float* __restrict__ b31,
    const float* __restrict__ w32, const float* __restrict__ b32,
    float* __restrict__ out)
{
    __shared__ ull   w12s[HH][HH];   // packed (m1w[k][j], m2w[k][j])  8 KB
    __shared__ ull   b12s[HH], g12s[HH], be12s[HH];
    __shared__ float SM[2176];
    const int tid  = threadIdx.x;
    const int warp = tid >> 5, t = tid & 31;
    const int gtid = blockIdx.x * TPB + tid;
    const int* src = ei;
    const int* dst = ei + EE;

    for (int i = tid; i < HH * HH; i += TPB)
        w12s[i / HH][i % HH] = packf2(m1w[i], m2w[i]);
    if (tid < HH) {
        b12s[tid]  = packf2(m1b[tid],  m2b[tid]);
        g12s[tid]  = packf2(m1g[tid],  m2g[tid]);
        be12s[tid] = packf2(m1be[tid], m2be[tid]);
    }
    __syncthreads();

    // ---- P5: two threads per edge; each owns 16 output columns ----
    {
        const int half = tid & 1;                // column half: [half*16, half*16+16)
        const int jo   = half * 16;
        const int slot = gtid >> 1;              // edge-slot id, < HALFSLOTS
        #pragma unroll
        for (int pass = 0; pass < 2; pass++) {
            int e = slot + pass * HALFSLOTS;
            if (e < EE) {
                int s = src[e], d = dst[e];
                const float4* hs4 = reinterpret_cast<const float4*>(d_h + s * HH);
                const float4* hd4 = reinterpret_cast<const float4*>(d_h + d * HH);
                float xe[HH];
                #pragma unroll
                for (int q = 0; q < 8; q++) {
                    float4 a = hs4[q], b = hd4[q];
                    xe[4 * q + 0] = a.x * b.x;
                    xe[4 * q + 1] = a.y * b.y;
                    xe[4 * q + 2] = a.z * b.z;
                    xe[4 * q + 3] = a.w * b.w;
                }
                ull y[16];
                #pragma unroll
                for (int j = 0; j < 16; j++) y[j] = b12s[jo + j];
                #pragma unroll
                for (int k = 0; k < HH; k++) {
                    ull xk = packf2(xe[k], xe[k]);
                    const ulonglong2* wr = reinterpret_cast<const ulonglong2*>(&w12s[k][jo]);
                    #pragma unroll
                    for (int j2 = 0; j2 < 8; j2++) {
                        ulonglong2 w2 = wr[j2];
                        y[2 * j2]     = fma2(xk, w2.x, y[2 * j2]);
                        y[2 * j2 + 1] = fma2(xk, w2.y, y[2 * j2 + 1]);
                    }
                }
                // LN stats over this thread's 16 columns (4-way trees)
                ull sa = y[0], sb = y[1], sc = y[2], sd = y[3];
                ull qa = mul2(y[0], y[0]), qb = mul2(y[1], y[1]);
                ull qc = mul2(y[2], y[2]), qd = mul2(y[3], y[3]);
                #pragma unroll
                for (int j = 4; j < 16; j += 4) {
                    sa = add2(sa, y[j]);     qa = fma2(y[j],     y[j],     qa);
                    sb = add2(sb, y[j + 1]); qb = fma2(y[j + 1], y[j + 1], qb);
                    sc = add2(sc, y[j + 2]); qc = fma2(y[j + 2], y[j + 2], qc);
                    sd = add2(sd, y[j + 3]); qd = fma2(y[j + 3], y[j + 3], qd);
                }
                ull s12 = add2(add2(sa, sb), add2(sc, sd));
                ull q12 = add2(add2(qa, qb), add2(qc, qd));
                // combine with partner thread (lane^1): full 32-column stats
                s12 = add2(s12, __shfl_xor_sync(FULL, s12, 1));
                q12 = add2(q12, __shfl_xor_sync(FULL, q12, 1));
                const ull c32 = packf2(1.f / 32.f, 1.f / 32.f);
                ull mu12 = mul2(s12, c32);
                ull nmu  = mu12 ^ 0x8000000080000000ULL;          // negate both halves
                ull v12  = fma2(mu12, nmu, mul2(q12, c32));       // E[y^2] - mu^2
                float v1, v2;
                unpackf2(v12, v1, v2);
                ull inv12 = packf2(rsqrtf(v1 + 1e-5f), rsqrtf(v2 + 1e-5f));
                float4* x1p = reinterpret_cast<float4*>(d_x1 + e * HH + jo);
                float4* x2p = reinterpret_cast<float4*>(d_x2 + e * HH + jo);
                #pragma unroll
                for (int q = 0; q < 4; q++) {
                    float4 r1, r2;
                    float a0, a1, a2, a3, b0, b1v, b2v, b3;
                    ull o0 = fma2(mul2(add2(y[4 * q + 0], nmu), inv12), g12s[jo + 4 * q + 0], be12s[jo + 4 * q + 0]);
                    ull o1 = fma2(mul2(add2(y[4 * q + 1], nmu), inv12), g12s[jo + 4 * q + 1], be12s[jo + 4 * q + 1]);
                    ull o2 = fma2(mul2(add2(y[4 * q + 2], nmu), inv12), g12s[jo + 4 * q + 2], be12s[jo + 4 * q + 2]);
                    ull o3 = fma2(mul2(add2(y[4 * q + 3], nmu), inv12), g12s[jo + 4 * q + 3], be12s[jo + 4 * q + 3]);
                    unpackf2(o0, a0, b0); unpackf2(o1, a1, b1v);
                    unpackf2(o2, a2, b2v); unpackf2(o3, a3, b3);
                    r1.x = fmaxf(a0, 0.f); r1.y = fmaxf(a1, 0.f);
                    r1.z = fmaxf(a2, 0.f); r1.w = fmaxf(a3, 0.f);
                    r2.x = fmaxf(b0, 0.f); r2.y = fmaxf(b1v, 0.f);
                    r2.z = fmaxf(b2v, 0.f); r2.w = fmaxf(b3, 0.f);
                    x1p[q] = r1;
                    x2p[q] = r2;
                }
            }
        }
    }
    gridbar();

    // ---- P6: posval join + head (pairs spread across all blocks) ----
    for (int i = tid; i < 2 * HH * HH; i += TPB) SM[i] = w31[i];
    if (tid < HH) { SM[2048 + tid] = w32[tid]; SM[2080 + tid] = b31[tid]; }
    __syncthreads();
    int p = blockIdx.x + GRID * warp;            // balanced over SMs
    if (p < PP) {
        int a = pos[p], b = pos[PP + p];
        float acc = 0.f;
        int st = d_outptr[a], en = d_outptr[a + 1];
        int base_a = a * NN;
        for (int base = st; base < en; base += 32) {
            int i = base + t;
            int e1 = -1, e2 = 0;
            if (i < en) {
                e1 = d_outlist[i];
                int n = dst[e1];
                if (d_M[base_a + n] == e1 + 1)       // dedupe: slot owner only
                    e2 = d_M[n * NN + b];
            }
            unsigned mask = __ballot_sync(FULL, e2 > 0);
            while (mask) {
                int j = __ffs(mask) - 1; mask &= mask - 1;
                int E1 = __shfl_sync(FULL, e1, j);
                int E2 = __shfl_sync(FULL, e2, j) - 1;
                acc = fmaf(d_x2[E1 * HH + t], d_x1[E2 * HH + t], acc);
            }
        }
        float xx = d_h[a * HH + t] * d_h[b * HH + t];
        float z1 = SM[2080 + t];
        #pragma unroll
        for (int k = 0; k < HH; k++) z1 = fmaf(__shfl_sync(FULL, acc, k), SM[k * HH + t], z1);
        #pragma unroll
        for (int k = 0; k < HH; k++) z1 = fmaf(__shfl_sync(FULL, xx, k), SM[(HH + k) * HH + t], z1);
        z1 = fmaxf(z1, 0.f);
        float r = wsum(z1 * SM[2048 + t]);
        if (t == 0) out[p] = r + b32[0];
    }
}

// ---------------- launch ----------------
extern "C" void kernel_launch(void* const* d_in, const int* in_sizes, int n_in,
                              void* d_out, int out_size) {
    const float* x    = (const float*)d_in[0];
    const int*   ei   = (const int*)  d_in[1];
    const int*   pos  = (const int*)  d_in[2];
    const float* W1   = (const float*)d_in[3];
    const float* b1   = (const float*)d_in[4];
    const float* W2   = (const float*)d_in[5];
    const float* b2   = (const float*)d_in[6];
    const float* m1w  = (const float*)d_in[7];
    const float* m1b  = (const float*)d_in[8];
    const float* m1g  = (const float*)d_in[9];
    const float* m1be = (const float*)d_in[10];
    const float* m2w  = (const float*)d_in[11];
    const float* m2b  = (const float*)d_in[12];
    const float* m2g  = (const float*)d_in[13];
    const float* m2be = (const float*)d_in[14];
    const float* m3w1 = (const float*)d_in[15];
    const float* m3b1 = (const float*)d_in[16];
    const float* m3w2 = (const float*)d_in[17];
    const float* m3b2 = (const float*)d_in[18];
    float* out = (float*)d_out;

    megaA_k<<<GRID, TPA>>>(x, ei, W1, b1, W2, b2);
    megaB_k<<<GRID, TPB>>>(ei, pos, m1w, m1b, m1g, m1be, m2w, m2b, m2g, m2be,
                           m3w1, m3b1, m3w2, m3b2, out);
}

// round 10
// speedup vs baseline: 1.1146x; 1.1146x over previous
#include <cuda_runtime.h>
#include <math.h>

#define NN 2048
#define FF 128
#define HH 32
#define EE 65536
#define PP 768
#define FULL 0xffffffffu
#define GRID 148
#define TPA 1024
#define TPB 512
#define NTA (GRID * TPA)

typedef unsigned long long ull;

// ---------------- device scratch (no allocations allowed) ----------------
// d_M: 0 = empty, else edge_id+1. Zero at module load. Each launch REWRITES
// exactly the same slot set {(src[e],dst[e])} before any read, so stale values
// from a previous replay are always overwritten -> no cleanup pass needed.
__device__ int   d_M[NN * NN];
__device__ int   d_deg[NN];
__device__ int   d_cnt[NN];
__device__ int   d_curs[NN];
__device__ int   d_curd[NN];
__device__ int   d_outptr[NN + 1];
__device__ int   d_inptr[NN + 1];
__device__ int   d_outlist[EE];
__device__ int   d_inlist[EE];
__device__ float d_dinv[NN];
__device__ float d_t1[NN * HH];
__device__ float d_t2[NN * HH];
__device__ __align__(16) float d_h[NN * HH];
__device__ __align__(16) float d_x1[EE * HH];
__device__ __align__(16) float d_x2[EE * HH];
__device__ unsigned          bar_cnt;
__device__ volatile unsigned bar_gen;

__device__ __forceinline__ void gridbar() {
    __syncthreads();
    if (threadIdx.x == 0) {
        __threadfence();
        unsigned g = bar_gen;
        if (atomicAdd(&bar_cnt, 1u) == GRID - 1u) {
            bar_cnt = 0;
            __threadfence();
            bar_gen = g + 1u;
        } else {
            while (bar_gen == g) __nanosleep(32);
        }
        __threadfence();
    }
    __syncthreads();
}

__device__ __forceinline__ float wsum(float v) {
    #pragma unroll
    for (int o = 16; o; o >>= 1) v += __shfl_xor_sync(FULL, v, o);
    return v;
}

__device__ __forceinline__ ull packf2(float lo, float hi) {
    ull r;
    asm("mov.b64 %0, {%1, %2};" : "=l"(r) : "f"(lo), "f"(hi));
    return r;
}
__device__ __forceinline__ void unpackf2(ull v, float& lo, float& hi) {
    asm("mov.b64 {%0, %1}, %2;" : "=f"(lo), "=f"(hi) : "l"(v));
}
__device__ __forceinline__ ull fma2(ull a, ull b, ull c) {
    ull d;
    asm("fma.rn.f32x2 %0, %1, %2, %3;" : "=l"(d) : "l"(a), "l"(b), "l"(c));
    return d;
}
__device__ __forceinline__ ull add2(ull a, ull b) {
    ull d;
    asm("add.rn.f32x2 %0, %1, %2;" : "=l"(d) : "l"(a), "l"(b));
    return d;
}
__device__ __forceinline__ ull mul2(ull a, ull b) {
    ull d;
    asm("mul.rn.f32x2 %0, %1, %2;" : "=l"(d) : "l"(a), "l"(b));
    return d;
}
// packed butterfly reduction: 2 SHFL + 1 FADD2 per step
__device__ __forceinline__ ull wsum2(ull v) {
    #pragma unroll
    for (int o = 16; o; o >>= 1) v = add2(v, __shfl_xor_sync(FULL, v, o));
    return v;
}

__device__ __forceinline__ int wscan_incl(int v, int lane) {
    #pragma unroll
    for (int o = 1; o < 32; o <<= 1) {
        int n = __shfl_up_sync(FULL, v, o);
        if (lane >= o) v += n;
    }
    return v;
}

// ================= megaA: CSR build + both GCN layers =================
__global__ void __launch_bounds__(TPA, 1) megaA_k(
    const float* __restrict__ x,  const int* __restrict__ ei,
    const float* __restrict__ W1, const float* __restrict__ b1,
    const float* __restrict__ W2, const float* __restrict__ b2)
{
    __shared__ float SM[4096];
    __shared__ int wt[32], wt2[32];
    const int tid  = threadIdx.x;
    const int warp = tid >> 5, t = tid & 31;
    const int gtid = blockIdx.x * TPA + tid;
    const int* src = ei;
    const int* dst = ei + EE;

    // ---- P0: gemm1 (t1 = x @ W1) overlapped with degrees + M scatter ----
    for (int i = tid; i < FF * HH; i += TPA) SM[i] = W1[i];
    __syncthreads();
    for (int e = gtid; e < EE; e += NTA) {       // fire atomics first
        int s = src[e], d = dst[e];
        atomicAdd(&d_deg[d], 1);
        atomicAdd(&d_cnt[s], 1);
        d_M[s * NN + d] = e + 1;   // duplicate (s,d) race: value-equivalent winners
    }
    {
        int row = warp * GRID + blockIdx.x;      // balanced across blocks
        if (row < NN) {
            const float* xr = x + row * FF;
            float xa = xr[t], xb = xr[32 + t], xc = xr[64 + t], xd = xr[96 + t];
            float acc = 0.f;
            #pragma unroll
            for (int k = 0; k < 32; k++) {
                acc = fmaf(__shfl_sync(FULL, xa, k), SM[k * HH + t], acc);
                acc = fmaf(__shfl_sync(FULL, xb, k), SM[(k + 32) * HH + t], acc);
                acc = fmaf(__shfl_sync(FULL, xc, k), SM[(k + 64) * HH + t], acc);
                acc = fmaf(__shfl_sync(FULL, xd, k), SM[(k + 96) * HH + t], acc);
            }
            d_t1[row * HH + t] = acc;
        }
    }
    gridbar();

    // ---- P1: block 0 fast scans (warp-shfl based) + dinv ----
    if (blockIdx.x == 0) {
        int a = d_cnt[2 * tid], b = d_cnt[2 * tid + 1];
        int c = d_deg[2 * tid], dd = d_deg[2 * tid + 1];
        int v1 = a + b, v2 = c + dd;
        int sc1 = wscan_incl(v1, t);
        int sc2 = wscan_incl(v2, t);
        if (t == 31) { wt[warp] = sc1; wt2[warp] = sc2; }
        __syncthreads();
        if (warp == 0) {
            int x1 = wscan_incl(wt[t], t);
            int x2 = wscan_incl(wt2[t], t);
            wt[t] = x1; wt2[t] = x2;
        }
        __syncthreads();
        int base1 = warp ? wt[warp - 1] : 0;
        int incl1 = base1 + sc1, excl1 = incl1 - v1;
        d_outptr[2 * tid] = excl1;
        d_outptr[2 * tid + 1] = excl1 + a;
        if (tid == 1023) d_outptr[2048] = incl1;
        int base2 = warp ? wt2[warp - 1] : 0;
        int incl2 = base2 + sc2, excl2 = incl2 - v2;
        d_inptr[2 * tid] = excl2;
        d_inptr[2 * tid + 1] = excl2 + c;
        if (tid == 1023) d_inptr[2048] = incl2;
        d_dinv[2 * tid]     = rsqrtf((float)(c + 1));
        d_dinv[2 * tid + 1] = rsqrtf((float)(dd + 1));
    }
    gridbar();

    // ---- P2: fill both CSR lists; zero deg/cnt ----
    if (gtid < NN) { d_deg[gtid] = 0; d_cnt[gtid] = 0; }
    for (int e = gtid; e < EE; e += NTA) {
        int s = src[e], d = dst[e];
        int ob = d_outptr[s], ib = d_inptr[d];
        int s1 = atomicAdd(&d_curs[s], 1);
        int s2 = atomicAdd(&d_curd[d], 1);
        d_outlist[ob + s1] = e;
        d_inlist[ib + s2]  = s;
    }
    gridbar();

    // ---- P3: gather layer1 (2 warps/node) + GEMM W2 ; zero cursors ----
    for (int i = tid; i < HH * HH; i += TPA) SM[i] = W2[i];
    if (gtid < NN) { d_curs[gtid] = 0; d_curd[gtid] = 0; }
    __syncthreads();
    {
        int pairid = warp >> 1, parity = warp & 1;
        int v = blockIdx.x * 16 + pairid;
        float part = 0.f;
        if (v < NN) {
            int st = d_inptr[v], en = d_inptr[v + 1];
            int i = st + parity;
            for (; i + 4 <= en; i += 4) {
                int s0 = d_inlist[i], s1 = d_inlist[i + 2];
                part = fmaf(d_t1[s0 * HH + t], d_dinv[s0], part);
                part = fmaf(d_t1[s1 * HH + t], d_dinv[s1], part);
            }
            for (; i < en; i += 2) {
                int s = d_inlist[i];
                part = fmaf(d_t1[s * HH + t], d_dinv[s], part);
            }
        }
        if (parity && v < NN) SM[1024 + pairid * 32 + t] = part;
        __syncthreads();
        if (!parity && v < NN) {
            float di = d_dinv[v];
            float hv = (part + SM[1024 + pairid * 32 + t] + d_t1[v * HH + t] * di) * di + b1[t];
            float y = 0.f;
            #pragma unroll
            for (int k = 0; k < HH; k++)
                y = fmaf(__shfl_sync(FULL, hv, k), SM[k * HH + t], y);
            d_t2[v * HH + t] = y;
        }
    }
    gridbar();

    // ---- P4: gather layer2 -> h ----
    {
        int pairid = warp >> 1, parity = warp & 1;
        int v = blockIdx.x * 16 + pairid;
        float part = 0.f;
        if (v < NN) {
            int st = d_inptr[v], en = d_inptr[v + 1];
            int i = st + parity;
            for (; i + 4 <= en; i += 4) {
                int s0 = d_inlist[i], s1 = d_inlist[i + 2];
                part = fmaf(d_t2[s0 * HH + t], d_dinv[s0], part);
                part = fmaf(d_t2[s1 * HH + t], d_dinv[s1], part);
            }
            for (; i < en; i += 2) {
                int s = d_inlist[i];
                part = fmaf(d_t2[s * HH + t], d_dinv[s], part);
            }
        }
        if (parity && v < NN) SM[pairid * 32 + t] = part;
        __syncthreads();
        if (!parity && v < NN) {
            float di = d_dinv[v];
            d_h[v * HH + t] = (part + SM[pairid * 32 + t] + d_t2[v * HH + t] * di) * di + b2[t];
        }
    }
}

// ========= megaB: warp-per-32-edges MLP (reg weights + SMEM xe) + posval =========
__global__ void __launch_bounds__(TPB, 1) megaB_k(
    const int* __restrict__ ei,  const int* __restrict__ pos,
    const float* __restrict__ m1w, const float* __restrict__ m1b,
    const float* __restrict__ m1g, const float* __restrict__ m1be,
    const float* __restrict__ m2w, const float* __restrict__ m2b,
    const float* __restrict__ m2g, const float* __restrict__ m2be,
    const float* __restrict__ w31, const float* __restrict__ b31,
    const float* __restrict__ w32, const float* __restrict__ b32,
    float* __restrict__ out)
{
    __shared__ ull   xes[16][8][32];   // warp-private xe staging, 32 KB
    __shared__ float SM[2176];
    const int tid  = threadIdx.x;
    const int warp = tid >> 5, t = tid & 31;
    const int gw   = blockIdx.x * 16 + warp;   // 2368 warps; first 2048 own edges
    const int* src = ei;
    const int* dst = ei + EE;

    // ---- P5: warp owns edges [32*gw, 32*gw+32); weights live in registers ----
    ull w12[HH];                               // packed (m1w[k][t], m2w[k][t])
    #pragma unroll
    for (int k = 0; k < HH; k++) w12[k] = packf2(m1w[k * HH + t], m2w[k * HH + t]);
    ull b12  = packf2(m1b[t],  m2b[t]);
    ull g12  = packf2(m1g[t],  m2g[t]);
    ull be12 = packf2(m1be[t], m2be[t]);
    const ull c32 = packf2(1.f / 32.f, 1.f / 32.f);

    if (gw < EE / 32) {
        const int eb = gw * 32;
        int s_t = src[eb + t], d_t = dst[eb + t];   // coalesced edge metadata
        #pragma unroll
        for (int sb = 0; sb < 4; sb++) {
            // Phase A: stage 8 edges' xe rows (coalesced h row loads)
            #pragma unroll
            for (int j = 0; j < 8; j++) {
                int jj = sb * 8 + j;
                int sj = __shfl_sync(FULL, s_t, jj);
                int dj = __shfl_sync(FULL, d_t, jj);
                float xe = d_h[sj * HH + t] * d_h[dj * HH + t];
                xes[warp][j][t] = packf2(xe, xe);
            }
            __syncwarp();
            // Phase B: 8 independent packed accumulator chains, zero weight LDS
            ull y[8];
            #pragma unroll
            for (int j = 0; j < 8; j++) y[j] = b12;
            #pragma unroll
            for (int j = 0; j < 8; j++) {
                const ulonglong2* xp = reinterpret_cast<const ulonglong2*>(&xes[warp][j][0]);
                #pragma unroll
                for (int kk = 0; kk < 16; kk++) {
                    ulonglong2 a2 = xp[kk];          // broadcast LDS.128
                    y[j] = fma2(a2.x, w12[2 * kk],     y[j]);
                    y[j] = fma2(a2.y, w12[2 * kk + 1], y[j]);
                }
            }
            __syncwarp();                             // xes dead; safe to refill next sb
            // Phase C: 8 interleaved packed LayerNorms + relu + store
            #pragma unroll
            for (int j = 0; j < 8; j++) {
                int e = eb + sb * 8 + j;
                ull s12 = wsum2(y[j]);
                ull q12 = wsum2(mul2(y[j], y[j]));
                ull mu12 = mul2(s12, c32);
                ull nmu  = mu12 ^ 0x8000000080000000ULL;       // negate both halves
                ull v12  = fma2(mu12, nmu, mul2(q12, c32));    // E[y^2] - mu^2
                float v1, v2;
                unpackf2(v12, v1, v2);
                ull inv12 = packf2(rsqrtf(v1 + 1e-5f), rsqrtf(v2 + 1e-5f));
                ull o12 = fma2(mul2(add2(y[j], nmu), inv12), g12, be12);
                float o1, o2;
                unpackf2(o12, o1, o2);
                d_x1[e * HH + t] = fmaxf(o1, 0.f);    // coalesced 128B rows
                d_x2[e * HH + t] = fmaxf(o2, 0.f);
            }
        }
    }
    gridbar();

    // ---- P6: posval join + head (pairs spread across all blocks) ----
    for (int i = tid; i < 2 * HH * HH; i += TPB) SM[i] = w31[i];
    if (tid < HH) { SM[2048 + tid] = w32[tid]; SM[2080 + tid] = b31[tid]; }
    __syncthreads();
    int p = blockIdx.x + GRID * warp;            // balanced over SMs
    if (p < PP) {
        int a = pos[p], b = pos[PP + p];
        float acc = 0.f;
        int st = d_outptr[a], en = d_outptr[a + 1];
        int base_a = a * NN;
        for (int base = st; base < en; base += 32) {
            int i = base + t;
            int e1 = -1, e2 = 0;
            if (i < en) {
                e1 = d_outlist[i];
                int n = dst[e1];
                if (d_M[base_a + n] == e1 + 1)       // dedupe: slot owner only
                    e2 = d_M[n * NN + b];
            }
            unsigned mask = __ballot_sync(FULL, e2 > 0);
            while (mask) {
                int j = __ffs(mask) - 1; mask &= mask - 1;
                int E1 = __shfl_sync(FULL, e1, j);
                int E2 = __shfl_sync(FULL, e2, j) - 1;
                acc = fmaf(d_x2[E1 * HH + t], d_x1[E2 * HH + t], acc);
            }
        }
        float xx = d_h[a * HH + t] * d_h[b * HH + t];
        float z1 = SM[2080 + t];
        #pragma unroll
        for (int k = 0; k < HH; k++) z1 = fmaf(__shfl_sync(FULL, acc, k), SM[k * HH + t], z1);
        #pragma unroll
        for (int k = 0; k < HH; k++) z1 = fmaf(__shfl_sync(FULL, xx, k), SM[(HH + k) * HH + t], z1);
        z1 = fmaxf(z1, 0.f);
        float r = wsum(z1 * SM[2048 + t]);
        if (t == 0) out[p] = r + b32[0];
    }
}

// ---------------- launch ----------------
extern "C" void kernel_launch(void* const* d_in, const int* in_sizes, int n_in,
                              void* d_out, int out_size) {
    const float* x    = (const float*)d_in[0];
    const int*   ei   = (const int*)  d_in[1];
    const int*   pos  = (const int*)  d_in[2];
    const float* W1   = (const float*)d_in[3];
    const float* b1   = (const float*)d_in[4];
    const float* W2   = (const float*)d_in[5];
    const float* b2   = (const float*)d_in[6];
    const float* m1w  = (const float*)d_in[7];
    const float* m1b  = (const float*)d_in[8];
    const float* m1g  = (const float*)d_in[9];
    const float* m1be = (const float*)d_in[10];
    const float* m2w  = (const float*)d_in[11];
    const float* m2b  = (const float*)d_in[12];
    const float* m2g  = (const float*)d_in[13];
    const float* m2be = (const float*)d_in[14];
    const float* m3w1 = (const float*)d_in[15];
    const float* m3b1 = (const float*)d_in[16];
    const float* m3w2 = (const float*)d_in[17];
    const float* m3b2 = (const float*)d_in[18];
    float* out = (float*)d_out;

    megaA_k<<<GRID, TPA>>>(x, ei, W1, b1, W2, b2);
    megaB_k<<<GRID, TPB>>>(ei, pos, m1w, m1b, m1g, m1be, m2w, m2b, m2g, m2be,
                           m3w1, m3b1, m3w2, m3b2, out);
}